// round 6
// baseline (speedup 1.0000x reference)
#include <cuda_runtime.h>
#include <cstdint>

#define N 4096
#define D 128
#define BHALF 2048
#define INV_T 14.285714285714285714f  /* 1/0.07 */
#define GEMM_BLOCKS 528

// ---------------- scratch (static device globals; no allocation) ----------------
__device__ __align__(16) float    g_f[N * D];      // L2-normalized features, fp32
__device__ __align__(16) unsigned g_ftf[N * D];    // tf32-rounded copies (bit pattern)
__device__ int    g_cnt[N];
__device__ int    g_sidx[N * 64];
__device__ float  g_sval[N * 64];
__device__ float  g_partial[N * 32];               // [row][slot] coalesced for rowfix
__device__ float  g_lp[N];

// ---------------- K1: L2 normalize + tf32 copy (warp per row) ----------------
__global__ void __launch_bounds__(512) k_norm(const float* __restrict__ feat) {
    const int wid = threadIdx.x >> 5, lane = threadIdx.x & 31;
    const int i = blockIdx.x * 16 + wid;
    float4 v = *(const float4*)(feat + (size_t)i * D + lane * 4);
    float s = v.x * v.x + v.y * v.y + v.z * v.z + v.w * v.w;
    #pragma unroll
    for (int o = 16; o; o >>= 1) s += __shfl_xor_sync(0xffffffffu, s, o);
    float r = sqrtf(s);
    float4 f = make_float4(v.x / r, v.y / r, v.z / r, v.w / r);
    *(float4*)(g_f + (size_t)i * D + lane * 4) = f;
    uint4 tf;
    asm("cvt.rna.tf32.f32 %0, %1;" : "=r"(tf.x) : "f"(f.x));
    asm("cvt.rna.tf32.f32 %0, %1;" : "=r"(tf.y) : "f"(f.y));
    asm("cvt.rna.tf32.f32 %0, %1;" : "=r"(tf.z) : "f"(f.z));
    asm("cvt.rna.tf32.f32 %0, %1;" : "=r"(tf.w) : "f"(f.w));
    *(uint4*)(g_ftf + (size_t)i * D + lane * 4) = tf;
}

// ---------------- fused main kernel: gemm blocks [0,528) + sparsemax blocks [528,4624) ----------------
__device__ __forceinline__ void mma_tf32(float c[4], const unsigned a[4], const unsigned b[2]) {
    asm volatile(
        "mma.sync.aligned.m16n8k8.row.col.f32.tf32.tf32.f32 "
        "{%0,%1,%2,%3}, {%4,%5,%6,%7}, {%8,%9}, {%0,%1,%2,%3};\n"
        : "+f"(c[0]), "+f"(c[1]), "+f"(c[2]), "+f"(c[3])
        : "r"(a[0]), "r"(a[1]), "r"(a[2]), "r"(a[3]), "r"(b[0]), "r"(b[1]));
}

#define LDA 36
#define CAND_MAX 128

__global__ void __launch_bounds__(256) k_main(const float* __restrict__ attn,
                                              float* __restrict__ outm) {
    // gemm smem
    __shared__ __align__(16) unsigned As[128 * LDA];
    __shared__ __align__(16) unsigned Bs[128 * LDA];
    __shared__ float sZr[128];
    __shared__ float sZc[4][128];
    // sparsemax smem (small, separate; total ~41KB)
    __shared__ float wred[8];
    __shared__ int   wcnt[8];
    __shared__ float s_max, s_tau;
    __shared__ int   s_ccnt, s_fb;
    __shared__ int   s_cidx[CAND_MAX];
    __shared__ float s_cval[CAND_MAX];

    const int tid = threadIdx.x;

    if (blockIdx.x < GEMM_BLOCKS) {
        // ===================== GEMM branch =====================
        int t = blockIdx.x, bi = 0;
        while (t >= 32 - bi) { t -= 32 - bi; bi++; }
        const int bj = bi + t;
        const bool diag = (bi == bj);

        const int lane = tid & 31, wid = tid >> 5;
        const int wm = wid >> 1, wn = wid & 1;
        const int g = lane >> 2, t4 = lane & 3;

        if (tid < 128) sZr[tid] = 0.0f;

        float acc[2][8][4];
        #pragma unroll
        for (int mt = 0; mt < 2; mt++)
            #pragma unroll
            for (int nt = 0; nt < 8; nt++)
                #pragma unroll
                for (int k = 0; k < 4; k++) acc[mt][nt][k] = 0.0f;

        const int lr = tid >> 1;
        const int lh = tid & 1;
        const unsigned* Bp = diag ? As : Bs;

        for (int kc = 0; kc < 4; kc++) {
            #pragma unroll
            for (int q = 0; q < 4; q++) {
                int cv = lh * 4 + q;
                uint4 va = *(const uint4*)(g_ftf + ((size_t)(bi * 128 + lr) * D + kc * 32 + cv * 4));
                *(uint4*)(As + lr * LDA + cv * 4) = va;
                if (!diag) {
                    uint4 vb = *(const uint4*)(g_ftf + ((size_t)(bj * 128 + lr) * D + kc * 32 + cv * 4));
                    *(uint4*)(Bs + lr * LDA + cv * 4) = vb;
                }
            }
            __syncthreads();

            #pragma unroll
            for (int ks = 0; ks < 4; ks++) {
                unsigned a[2][4], b[8][2];
                #pragma unroll
                for (int mt = 0; mt < 2; mt++) {
                    int r0 = wm * 32 + mt * 16 + g;
                    a[mt][0] = As[r0 * LDA + ks * 8 + t4];
                    a[mt][1] = As[(r0 + 8) * LDA + ks * 8 + t4];
                    a[mt][2] = As[r0 * LDA + ks * 8 + t4 + 4];
                    a[mt][3] = As[(r0 + 8) * LDA + ks * 8 + t4 + 4];
                }
                #pragma unroll
                for (int nt = 0; nt < 8; nt++) {
                    int c0 = wn * 64 + nt * 8 + g;
                    b[nt][0] = Bp[c0 * LDA + ks * 8 + t4];
                    b[nt][1] = Bp[c0 * LDA + ks * 8 + t4 + 4];
                }
                #pragma unroll
                for (int mt = 0; mt < 2; mt++)
                    #pragma unroll
                    for (int nt = 0; nt < 8; nt++) mma_tf32(acc[mt][nt], a[mt], b[nt]);
            }
            __syncthreads();
        }

        const int ibase = bi * 128, jbase = bj * 128;
        float cp0[8], cp1[8];
        #pragma unroll
        for (int nt = 0; nt < 8; nt++) { cp0[nt] = 0.f; cp1[nt] = 0.f; }

        #pragma unroll
        for (int mt = 0; mt < 2; mt++) {
            int r0 = wm * 32 + mt * 16 + g;
            int gi0 = ibase + r0, gi1 = gi0 + 8;
            float rs0 = 0.f, rs1 = 0.f;
            #pragma unroll
            for (int nt = 0; nt < 8; nt++) {
                int c0 = wn * 64 + nt * 8 + t4 * 2;
                int gj0 = jbase + c0, gj1 = gj0 + 1;
                float e0 = __expf((acc[mt][nt][0] - 1.0f) * INV_T);
                float e1 = __expf((acc[mt][nt][1] - 1.0f) * INV_T);
                float e2 = __expf((acc[mt][nt][2] - 1.0f) * INV_T);
                float e3 = __expf((acc[mt][nt][3] - 1.0f) * INV_T);
                if (diag) {
                    if (gj0 == gi0) e0 = 0.f;
                    if (gj1 == gi0) e1 = 0.f;
                    if (gj0 == gi1) e2 = 0.f;
                    if (gj1 == gi1) e3 = 0.f;
                }
                rs0 += e0 + e1; rs1 += e2 + e3;
                cp0[nt] += e0 + e2; cp1[nt] += e1 + e3;
            }
            rs0 += __shfl_xor_sync(0xffffffffu, rs0, 1);
            rs0 += __shfl_xor_sync(0xffffffffu, rs0, 2);
            rs1 += __shfl_xor_sync(0xffffffffu, rs1, 1);
            rs1 += __shfl_xor_sync(0xffffffffu, rs1, 2);
            if (t4 == 0) {
                atomicAdd(&sZr[r0], rs0);
                atomicAdd(&sZr[r0 + 8], rs1);
            }
        }

        if (!diag) {
            #pragma unroll
            for (int nt = 0; nt < 8; nt++) {
                #pragma unroll
                for (int o = 4; o <= 16; o <<= 1) {
                    cp0[nt] += __shfl_xor_sync(0xffffffffu, cp0[nt], o);
                    cp1[nt] += __shfl_xor_sync(0xffffffffu, cp1[nt], o);
                }
            }
            if (g == 0) {
                #pragma unroll
                for (int nt = 0; nt < 8; nt++) {
                    int c = wn * 64 + nt * 8 + t4 * 2;
                    sZc[wm][c] = cp0[nt];
                    sZc[wm][c + 1] = cp1[nt];
                }
            }
        }
        __syncthreads();

        if (tid < 128) {
            g_partial[(size_t)(ibase + tid) * 32 + bj] = sZr[tid];
            if (!diag) {
                float cs = ((sZc[0][tid] + sZc[1][tid]) + sZc[2][tid]) + sZc[3][tid];
                g_partial[(size_t)(jbase + tid) * 32 + bi] = cs;
            }
        }
    } else {
        // ===================== sparsemax branch (256 threads, 16 elems/thread) =====================
        const int i = blockIdx.x - GEMM_BLOCKS;
        const int j1 = i & (BHALF - 1);
        const int j2 = j1 + BHALF;
        const float4* row4 = (const float4*)(attn + (size_t)i * N);

        float z[16];
        float mx = -3.402823466e38f;
        #pragma unroll
        for (int it = 0; it < 4; it++) {
            int v = tid + it * 256;          // float4 index
            float4 r = row4[v];
            int j = v * 4;
            float z0 = (j     == j1 || j     == j2) ? 0.f : r.x * INV_T;
            float z1 = (j + 1 == j1 || j + 1 == j2) ? 0.f : r.y * INV_T;
            float z2 = (j + 2 == j1 || j + 2 == j2) ? 0.f : r.z * INV_T;
            float z3 = (j + 3 == j1 || j + 3 == j2) ? 0.f : r.w * INV_T;
            z[it * 4] = z0; z[it * 4 + 1] = z1; z[it * 4 + 2] = z2; z[it * 4 + 3] = z3;
            mx = fmaxf(mx, fmaxf(fmaxf(z0, z1), fmaxf(z2, z3)));
        }
        #pragma unroll
        for (int o = 16; o; o >>= 1) mx = fmaxf(mx, __shfl_xor_sync(0xffffffffu, mx, o));
        if ((tid & 31) == 0) wred[tid >> 5] = mx;
        if (tid == 0) s_ccnt = 0;
        __syncthreads();
        if (tid == 0) {
            float m = wred[0];
            for (int w = 1; w < 8; w++) m = fmaxf(m, wred[w]);
            s_max = m;
        }
        __syncthreads();

        const float thr = s_max - 1.0f;
        #pragma unroll
        for (int it = 0; it < 4; it++) {
            int j = (tid + it * 256) * 4;
            #pragma unroll
            for (int q = 0; q < 4; q++) {
                float v = z[it * 4 + q];
                if (v >= thr) {
                    int p = atomicAdd(&s_ccnt, 1);
                    if (p < CAND_MAX) { s_cidx[p] = j + q; s_cval[p] = v; }
                }
            }
        }
        __syncthreads();

        if (tid == 0) {
            int cnt = s_ccnt;
            s_fb = (cnt > CAND_MAX);
            if (!s_fb) {
                for (int a = 1; a < cnt; a++) {
                    float v = s_cval[a]; int ix = s_cidx[a];
                    int b = a - 1;
                    while (b >= 0 && (s_cval[b] < v || (s_cval[b] == v && s_cidx[b] > ix))) {
                        s_cval[b + 1] = s_cval[b]; s_cidx[b + 1] = s_cidx[b]; b--;
                    }
                    s_cval[b + 1] = v; s_cidx[b + 1] = ix;
                }
                float cum = 0.f, cumkz = 1.f; int kz = 1;
                for (int k = 1; k <= cnt; k++) {
                    float v = s_cval[k - 1];
                    cum += v;
                    if (1.0f + (float)k * v > cum) { kz = k; cumkz = cum; }
                }
                float tau = (cumkz - 1.0f) / (float)kz;
                s_tau = tau;
                g_cnt[i] = kz;
                int lim = kz < 64 ? kz : 64;
                for (int k = 0; k < lim; k++) {
                    g_sidx[i * 64 + k] = s_cidx[k];
                    g_sval[i * 64 + k] = s_cval[k] - tau;
                }
            }
        }
        __syncthreads();

        if (s_fb) {
            float tau = -3.402823466e38f;
            for (int iter = 0; iter < 64; iter++) {
                float s = 0.f; int c = 0;
                #pragma unroll
                for (int it = 0; it < 16; it++) {
                    float v = z[it];
                    if (v > tau) { s += v; c++; }
                }
                #pragma unroll
                for (int o = 16; o; o >>= 1) {
                    s += __shfl_xor_sync(0xffffffffu, s, o);
                    c += __shfl_xor_sync(0xffffffffu, c, o);
                }
                if ((tid & 31) == 0) { wred[tid >> 5] = s; wcnt[tid >> 5] = c; }
                __syncthreads();
                if (tid == 0) {
                    float S = 0.f; int C = 0;
                    for (int w = 0; w < 8; w++) { S += wred[w]; C += wcnt[w]; }
                    s_tau = (S - 1.0f) / (float)C;
                }
                __syncthreads();
                float tn = s_tau;
                if (tn == tau) break;
                tau = tn;
                __syncthreads();
            }
            if (tid == 0) g_cnt[i] = N;
            __syncthreads();
        }

        const float tau = s_tau;
        float* orow = outm + (size_t)i * N;
        #pragma unroll
        for (int it = 0; it < 4; it++) {
            int j = (tid + it * 256) * 4;
            orow[j]     = fmaxf(z[it * 4]     - tau, 0.f);
            orow[j + 1] = fmaxf(z[it * 4 + 1] - tau, 0.f);
            orow[j + 2] = fmaxf(z[it * 4 + 2] - tau, 0.f);
            orow[j + 3] = fmaxf(z[it * 4 + 3] - tau, 0.f);
        }
    }
}

// ---------------- K4: per-row corrections + log-prob (warp per row) ----------------
__global__ void __launch_bounds__(256) k_rowfix(const float* __restrict__ outm) {
    const int wid = threadIdx.x >> 5, lane = threadIdx.x & 31;
    const int i = blockIdx.x * 8 + wid;

    const float4 a = *(const float4*)(g_f + (size_t)i * D + lane * 4);

    auto dot = [&](int j) -> float {
        float4 b = *(const float4*)(g_f + (size_t)j * D + lane * 4);
        float p = a.x * b.x + a.y * b.y + a.z * b.z + a.w * b.w;
        #pragma unroll
        for (int o = 16; o; o >>= 1) p += __shfl_xor_sync(0xffffffffu, p, o);
        return p;
    };

    float simpos = (dot(i ^ BHALF) - 1.0f) * INV_T;

    int cnt = g_cnt[i];
    float corr = 0.0f;
    if (cnt <= 64) {
        for (int k = 0; k < cnt; k++) {
            int j = g_sidx[i * 64 + k];
            float m = g_sval[i * 64 + k];
            corr += m * __expf((dot(j) - 1.0f) * INV_T);
        }
    } else {
        for (int j = 0; j < N; j++) {
            float m = outm[(size_t)i * N + j];
            if (m > 0.0f) corr += m * __expf((dot(j) - 1.0f) * INV_T);
        }
    }

    float zp = g_partial[(size_t)i * 32 + lane];   // one coalesced 128B line per warp
    #pragma unroll
    for (int o = 16; o; o >>= 1) zp += __shfl_xor_sync(0xffffffffu, zp, o);

    if (lane == 0) g_lp[i] = simpos - logf(zp - corr);
}

// ---------------- K5: loss reduction (shuffle-based, 1 barrier) ----------------
__global__ void __launch_bounds__(512) k_loss(float* __restrict__ out, int moff) {
    __shared__ float sm[16];
    const int t = threadIdx.x, lane = t & 31, w = t >> 5;
    float s = 0.0f;
    #pragma unroll
    for (int k = 0; k < 8; k++) s += g_lp[t + k * 512];
    #pragma unroll
    for (int o = 16; o; o >>= 1) s += __shfl_xor_sync(0xffffffffu, s, o);
    if (lane == 0) sm[w] = s;
    __syncthreads();
    if (w == 0) {
        float v = (lane < 16) ? sm[lane] : 0.0f;
        #pragma unroll
        for (int o = 8; o; o >>= 1) v += __shfl_xor_sync(0xffffffffu, v, o);
        if (lane == 0) {
            float loss = -(v / 4096.0f);
            for (int q = 0; q < moff; q++) out[q] = loss;
        }
    }
}

// ---------------- launch ----------------
extern "C" void kernel_launch(void* const* d_in, const int* in_sizes, int n_in,
                              void* d_out, int out_size) {
    int fidx = (in_sizes[0] == N * D) ? 0 : 1;
    const float* feat = (const float*)d_in[fidx];
    const float* attn = (const float*)d_in[1 - fidx];
    float* out = (float*)d_out;

    long long nn = (long long)N * (long long)N;
    int moff = (int)((long long)out_size - nn);
    if (moff < 0) moff = 0;
    float* outm = out + moff;

    k_norm<<<N / 16, 512>>>(feat);
    k_main<<<GEMM_BLOCKS + N, 256>>>(attn, outm);
    k_rowfix<<<512, 256>>>(outm);
    k_loss<<<1, 512>>>(out, moff);
}